// round 8
// baseline (speedup 1.0000x reference)
#include <cuda_runtime.h>
#include <cuda_fp16.h>

#define NN   100000
#define INF  128
#define OUTF 64
#define NE_MAX 3200000
#define SCAN_B 1024
#define NBLK  ((NN + SCAN_B - 1) / SCAN_B)   // 98
#define WPAD  72

// Scratch (allocation-free rule: __device__ globals)
__device__ __half g_xws_h[(size_t)NN * OUTF]; // fp16 (X@W)*rsqrt(deg_out)
__device__ int    g_deg_out[NN];
__device__ int    g_deg_in[NN];
__device__ int    g_row_off[NN];
__device__ int    g_cursor[NN];
__device__ int    g_csr_src[NE_MAX];
__device__ int    g_blocksum[NBLK];
__device__ int    g_blockoff[NBLK];

// ---------------------------------------------------------------------------
__global__ void zero_kernel() {
    int t = blockIdx.x * blockDim.x + threadIdx.x;
    int stride = gridDim.x * blockDim.x;
    for (int j = t; j < NN; j += stride) {
        g_deg_out[j] = 0;
        g_deg_in[j]  = 0;
    }
}

// ---------------------------------------------------------------------------
__global__ void degree_kernel(const int* __restrict__ src,
                              const int* __restrict__ dst, int E) {
    int stride = gridDim.x * blockDim.x;
    for (int e = blockIdx.x * blockDim.x + threadIdx.x; e < E; e += stride) {
        int s = src[e], d = dst[e];
        if ((unsigned)s < NN) atomicAdd(&g_deg_out[s], 1);
        if ((unsigned)d < NN) atomicAdd(&g_deg_in[d],  1);
    }
}

// ---------------------------------------------------------------------------
// Exclusive scan of g_deg_in -> g_row_off  (3 passes)
// ---------------------------------------------------------------------------
__global__ __launch_bounds__(SCAN_B) void scan_local_kernel() {
    __shared__ int sm[SCAN_B];
    int tid = threadIdx.x;
    int gid = blockIdx.x * SCAN_B + tid;
    int val = (gid < NN) ? g_deg_in[gid] : 0;
    sm[tid] = val;
    __syncthreads();
    #pragma unroll
    for (int off = 1; off < SCAN_B; off <<= 1) {
        int t = (tid >= off) ? sm[tid - off] : 0;
        __syncthreads();
        sm[tid] += t;
        __syncthreads();
    }
    if (gid < NN) g_row_off[gid] = sm[tid] - val;
    if (tid == SCAN_B - 1) g_blocksum[blockIdx.x] = sm[tid];
}

__global__ __launch_bounds__(128) void scan_blocks_kernel() {
    __shared__ int sm[128];
    int t = threadIdx.x;
    int val = (t < NBLK) ? g_blocksum[t] : 0;
    sm[t] = val;
    __syncthreads();
    #pragma unroll
    for (int off = 1; off < 128; off <<= 1) {
        int u = (t >= off) ? sm[t - off] : 0;
        __syncthreads();
        sm[t] += u;
        __syncthreads();
    }
    if (t < NBLK) g_blockoff[t] = sm[t] - val;
}

__global__ __launch_bounds__(SCAN_B) void scan_add_kernel() {
    int gid = blockIdx.x * SCAN_B + threadIdx.x;
    if (gid < NN) {
        int v = g_row_off[gid] + g_blockoff[blockIdx.x];
        g_row_off[gid] = v;
        g_cursor[gid]  = v;
    }
}

// ---------------------------------------------------------------------------
__global__ void csr_fill_kernel(const int* __restrict__ src,
                                const int* __restrict__ dst, int E) {
    int stride = gridDim.x * blockDim.x;
    for (int e = blockIdx.x * blockDim.x + threadIdx.x; e < E; e += stride) {
        int s = src[e], d = dst[e];
        if ((unsigned)s >= NN || (unsigned)d >= NN) continue;
        int pos = atomicAdd(&g_cursor[d], 1);
        g_csr_src[pos] = s;
    }
}

// ---------------------------------------------------------------------------
// Tensor-core GEMM: xws = fp16( (A @ W) * rsqrt(max(deg_out,1)) )
// mma.sync.m16n8k8 tf32. One warp = 16 rows x 64 cols.
// ---------------------------------------------------------------------------
__global__ __launch_bounds__(256) void gemm_mma_kernel(
    const float* __restrict__ A, const float* __restrict__ W, int n) {
    __shared__ unsigned Ws[INF][WPAD];
    int tid = threadIdx.x;
    for (int i = tid; i < INF * OUTF; i += 256) {
        int k = i >> 6, c = i & 63;
        unsigned t;
        asm("cvt.rna.tf32.f32 %0, %1;" : "=r"(t) : "f"(W[i]));
        Ws[k][c] = t;
    }
    __syncthreads();

    int warp = tid >> 5;
    int lane = tid & 31;
    int g  = lane >> 2;
    int tg = lane & 3;
    int row0 = (blockIdx.x * 8 + warp) * 16;

    int r_lo = row0 + g;
    int r_hi = row0 + g + 8;
    int r_lo_c = r_lo < n ? r_lo : n - 1;
    int r_hi_c = r_hi < n ? r_hi : n - 1;
    const float* Alo = A + (size_t)r_lo_c * INF;
    const float* Ahi = A + (size_t)r_hi_c * INF;

    float acc[8][4];
    #pragma unroll
    for (int nt = 0; nt < 8; nt++)
        #pragma unroll
        for (int c = 0; c < 4; c++) acc[nt][c] = 0.f;

    #pragma unroll
    for (int kk = 0; kk < 16; kk++) {
        int k0 = kk * 8;
        float a0f = __ldg(&Alo[k0 + tg]);
        float a1f = __ldg(&Ahi[k0 + tg]);
        float a2f = __ldg(&Alo[k0 + tg + 4]);
        float a3f = __ldg(&Ahi[k0 + tg + 4]);
        unsigned a0, a1, a2, a3;
        asm("cvt.rna.tf32.f32 %0, %1;" : "=r"(a0) : "f"(a0f));
        asm("cvt.rna.tf32.f32 %0, %1;" : "=r"(a1) : "f"(a1f));
        asm("cvt.rna.tf32.f32 %0, %1;" : "=r"(a2) : "f"(a2f));
        asm("cvt.rna.tf32.f32 %0, %1;" : "=r"(a3) : "f"(a3f));
        #pragma unroll
        for (int nt = 0; nt < 8; nt++) {
            unsigned b0 = Ws[k0 + tg][nt * 8 + g];
            unsigned b1 = Ws[k0 + tg + 4][nt * 8 + g];
            asm("mma.sync.aligned.m16n8k8.row.col.f32.tf32.tf32.f32 "
                "{%0,%1,%2,%3}, {%4,%5,%6,%7}, {%8,%9}, {%0,%1,%2,%3};"
                : "+f"(acc[nt][0]), "+f"(acc[nt][1]),
                  "+f"(acc[nt][2]), "+f"(acc[nt][3])
                : "r"(a0), "r"(a1), "r"(a2), "r"(a3), "r"(b0), "r"(b1));
        }
    }

    float s_lo = 1.f, s_hi = 1.f;
    if (r_lo < n) {
        int dg = g_deg_out[r_lo];
        s_lo = rsqrtf((float)(dg > 0 ? dg : 1));
    }
    if (r_hi < n) {
        int dg = g_deg_out[r_hi];
        s_hi = rsqrtf((float)(dg > 0 ? dg : 1));
    }
    #pragma unroll
    for (int nt = 0; nt < 8; nt++) {
        int col = nt * 8 + 2 * tg;
        if (r_lo < n) {
            __half2 h = __floats2half2_rn(acc[nt][0] * s_lo, acc[nt][1] * s_lo);
            *(__half2*)&g_xws_h[(size_t)r_lo * OUTF + col] = h;
        }
        if (r_hi < n) {
            __half2 h = __floats2half2_rn(acc[nt][2] * s_hi, acc[nt][3] * s_hi);
            *(__half2*)&g_xws_h[(size_t)r_hi * OUTF + col] = h;
        }
    }
}

// ---------------------------------------------------------------------------
// Aggregate: HALF-warp (16 lanes) per dst node; lane owns 4 output cols and
// loads uint2 (LDG.64). Per edge, 16 lanes fetch the 128B fp16 row (one L2
// line). fp32 accumulation; fused rsqrt(deg_in)+bias+relu; float4 stores.
// ---------------------------------------------------------------------------
__global__ __launch_bounds__(256) void aggregate_kernel(
    float* __restrict__ out, const float* __restrict__ b, int n) {
    int node = (blockIdx.x * blockDim.x + threadIdx.x) >> 4;
    if (node >= n) return;
    int l = threadIdx.x & 15;

    int start = g_row_off[node];
    int deg   = g_deg_in[node];

    float a0x = 0.f, a0y = 0.f, a1x = 0.f, a1y = 0.f;
    const uint2* base = (const uint2*)g_xws_h;   // 16 uint2 per row

    for (int e0 = 0; e0 < deg; e0 += 16) {
        int me  = e0 + l;
        int s   = (me < deg) ? __ldg(&g_csr_src[start + me]) : 0;
        int cnt = deg - e0; if (cnt > 16) cnt = 16;
        int j = 0;
        #pragma unroll 1
        for (; j + 2 <= cnt; j += 2) {
            int s0 = __shfl_sync(0xffffffffu, s, j + 0, 16);
            int s1 = __shfl_sync(0xffffffffu, s, j + 1, 16);
            uint2 u0 = __ldg(base + (size_t)s0 * 16 + l);
            uint2 u1 = __ldg(base + (size_t)s1 * 16 + l);
            float2 p0 = __half22float2(*(__half2*)&u0.x);
            float2 q0 = __half22float2(*(__half2*)&u0.y);
            float2 p1 = __half22float2(*(__half2*)&u1.x);
            float2 q1 = __half22float2(*(__half2*)&u1.y);
            a0x += p0.x + p1.x;  a0y += p0.y + p1.y;
            a1x += q0.x + q1.x;  a1y += q0.y + q1.y;
        }
        if (j < cnt) {
            int sj = __shfl_sync(0xffffffffu, s, j, 16);
            uint2 u = __ldg(base + (size_t)sj * 16 + l);
            float2 p = __half22float2(*(__half2*)&u.x);
            float2 q = __half22float2(*(__half2*)&u.y);
            a0x += p.x;  a0y += p.y;
            a1x += q.x;  a1y += q.y;
        }
    }

    float sc = rsqrtf((float)(deg > 0 ? deg : 1));
    float4 bb = __ldg((const float4*)b + l);
    float4 r;
    r.x = fmaxf(fmaf(a0x, sc, bb.x), 0.f);
    r.y = fmaxf(fmaf(a0y, sc, bb.y), 0.f);
    r.z = fmaxf(fmaf(a1x, sc, bb.z), 0.f);
    r.w = fmaxf(fmaf(a1y, sc, bb.w), 0.f);
    ((float4*)out)[(size_t)node * 16 + l] = r;
}

// ---------------------------------------------------------------------------
// Fork/join: GEMM (needs only deg_out) overlaps the scan+fill chain.
// ---------------------------------------------------------------------------
extern "C" void kernel_launch(void* const* d_in, const int* in_sizes, int n_in,
                              void* d_out, int out_size) {
    const float* in_feat = (const float*)d_in[0];
    const int*   src     = (const int*)d_in[1];
    const int*   dst     = (const int*)d_in[2];
    const float* W       = (const float*)d_in[3];
    const float* b       = (const float*)d_in[4];
    float*       out     = (float*)d_out;

    int n = in_sizes[0] / INF;
    int E = in_sizes[1];

    static cudaStream_t sA = nullptr;
    static cudaEvent_t  evD = nullptr, evF = nullptr;
    if (!sA) {   // one-time infra setup (first call is outside graph capture)
        cudaStreamCreateWithFlags(&sA, cudaStreamNonBlocking);
        cudaEventCreateWithFlags(&evD, cudaEventDisableTiming);
        cudaEventCreateWithFlags(&evF, cudaEventDisableTiming);
    }

    zero_kernel<<<512, 256>>>();
    degree_kernel<<<2048, 256>>>(src, dst, E);
    cudaEventRecord(evD, 0);

    // side stream: CSR build chain
    cudaStreamWaitEvent(sA, evD, 0);
    scan_local_kernel<<<NBLK, SCAN_B, 0, sA>>>();
    scan_blocks_kernel<<<1, 128, 0, sA>>>();
    scan_add_kernel<<<NBLK, SCAN_B, 0, sA>>>();
    csr_fill_kernel<<<2048, 256, 0, sA>>>(src, dst, E);
    cudaEventRecord(evF, sA);

    // main stream: GEMM overlaps the CSR build
    gemm_mma_kernel<<<(n + 127) / 128, 256>>>(in_feat, W, n);

    cudaStreamWaitEvent(0, evF, 0);
    aggregate_kernel<<<(n * 16 + 255) / 256, 256>>>(out, b, n);
}

// round 9
// speedup vs baseline: 1.2307x; 1.2307x over previous
#include <cuda_runtime.h>
#include <cuda_fp16.h>

#define NN   100000
#define INF  128
#define OUTF 64
#define NE_MAX 3200000
#define SCAN_B 1024
#define NBLK  ((NN + SCAN_B - 1) / SCAN_B)   // 98
#define WPAD  72

// Scratch (allocation-free rule: __device__ globals)
__device__ __half g_xws_h[(size_t)NN * OUTF]; // fp16 (X@W)*rsqrt(deg_out)
__device__ int    g_deg_out[NN];
__device__ int    g_deg_in[NN];
__device__ int    g_row_off[NN];
__device__ int    g_cursor[NN];
__device__ int    g_csr_src[NE_MAX];
__device__ int    g_blocksum[NBLK];
__device__ int    g_blockoff[NBLK];

// ---------------------------------------------------------------------------
__global__ void zero_kernel() {
    int t = blockIdx.x * blockDim.x + threadIdx.x;
    int stride = gridDim.x * blockDim.x;
    for (int j = t; j < NN; j += stride) {
        g_deg_out[j] = 0;
        g_deg_in[j]  = 0;
    }
}

// ---------------------------------------------------------------------------
__global__ void degree_kernel(const int* __restrict__ src,
                              const int* __restrict__ dst, int E) {
    int stride = gridDim.x * blockDim.x;
    for (int e = blockIdx.x * blockDim.x + threadIdx.x; e < E; e += stride) {
        int s = src[e], d = dst[e];
        if ((unsigned)s < NN) atomicAdd(&g_deg_out[s], 1);
        if ((unsigned)d < NN) atomicAdd(&g_deg_in[d],  1);
    }
}

// ---------------------------------------------------------------------------
// Exclusive scan of g_deg_in -> g_row_off  (3 passes)
// ---------------------------------------------------------------------------
__global__ __launch_bounds__(SCAN_B) void scan_local_kernel() {
    __shared__ int sm[SCAN_B];
    int tid = threadIdx.x;
    int gid = blockIdx.x * SCAN_B + tid;
    int val = (gid < NN) ? g_deg_in[gid] : 0;
    sm[tid] = val;
    __syncthreads();
    #pragma unroll
    for (int off = 1; off < SCAN_B; off <<= 1) {
        int t = (tid >= off) ? sm[tid - off] : 0;
        __syncthreads();
        sm[tid] += t;
        __syncthreads();
    }
    if (gid < NN) g_row_off[gid] = sm[tid] - val;
    if (tid == SCAN_B - 1) g_blocksum[blockIdx.x] = sm[tid];
}

__global__ __launch_bounds__(128) void scan_blocks_kernel() {
    __shared__ int sm[128];
    int t = threadIdx.x;
    int val = (t < NBLK) ? g_blocksum[t] : 0;
    sm[t] = val;
    __syncthreads();
    #pragma unroll
    for (int off = 1; off < 128; off <<= 1) {
        int u = (t >= off) ? sm[t - off] : 0;
        __syncthreads();
        sm[t] += u;
        __syncthreads();
    }
    if (t < NBLK) g_blockoff[t] = sm[t] - val;
}

__global__ __launch_bounds__(SCAN_B) void scan_add_kernel() {
    int gid = blockIdx.x * SCAN_B + threadIdx.x;
    if (gid < NN) {
        int v = g_row_off[gid] + g_blockoff[blockIdx.x];
        g_row_off[gid] = v;
        g_cursor[gid]  = v;
    }
}

// ---------------------------------------------------------------------------
__global__ void csr_fill_kernel(const int* __restrict__ src,
                                const int* __restrict__ dst, int E) {
    int stride = gridDim.x * blockDim.x;
    for (int e = blockIdx.x * blockDim.x + threadIdx.x; e < E; e += stride) {
        int s = src[e], d = dst[e];
        if ((unsigned)s >= NN || (unsigned)d >= NN) continue;
        int pos = atomicAdd(&g_cursor[d], 1);
        g_csr_src[pos] = s;
    }
}

// ---------------------------------------------------------------------------
// Tensor-core GEMM: xws = fp16( (A @ W) * rsqrt(max(deg_out,1)) )
// mma.sync.m16n8k8 tf32. One warp = 16 rows x 64 cols.
// ---------------------------------------------------------------------------
__global__ __launch_bounds__(256) void gemm_mma_kernel(
    const float* __restrict__ A, const float* __restrict__ W, int n) {
    __shared__ unsigned Ws[INF][WPAD];
    int tid = threadIdx.x;
    for (int i = tid; i < INF * OUTF; i += 256) {
        int k = i >> 6, c = i & 63;
        unsigned t;
        asm("cvt.rna.tf32.f32 %0, %1;" : "=r"(t) : "f"(W[i]));
        Ws[k][c] = t;
    }
    __syncthreads();

    int warp = tid >> 5;
    int lane = tid & 31;
    int g  = lane >> 2;
    int tg = lane & 3;
    int row0 = (blockIdx.x * 8 + warp) * 16;

    int r_lo = row0 + g;
    int r_hi = row0 + g + 8;
    int r_lo_c = r_lo < n ? r_lo : n - 1;
    int r_hi_c = r_hi < n ? r_hi : n - 1;
    const float* Alo = A + (size_t)r_lo_c * INF;
    const float* Ahi = A + (size_t)r_hi_c * INF;

    float acc[8][4];
    #pragma unroll
    for (int nt = 0; nt < 8; nt++)
        #pragma unroll
        for (int c = 0; c < 4; c++) acc[nt][c] = 0.f;

    #pragma unroll
    for (int kk = 0; kk < 16; kk++) {
        int k0 = kk * 8;
        float a0f = __ldg(&Alo[k0 + tg]);
        float a1f = __ldg(&Ahi[k0 + tg]);
        float a2f = __ldg(&Alo[k0 + tg + 4]);
        float a3f = __ldg(&Ahi[k0 + tg + 4]);
        unsigned a0, a1, a2, a3;
        asm("cvt.rna.tf32.f32 %0, %1;" : "=r"(a0) : "f"(a0f));
        asm("cvt.rna.tf32.f32 %0, %1;" : "=r"(a1) : "f"(a1f));
        asm("cvt.rna.tf32.f32 %0, %1;" : "=r"(a2) : "f"(a2f));
        asm("cvt.rna.tf32.f32 %0, %1;" : "=r"(a3) : "f"(a3f));
        #pragma unroll
        for (int nt = 0; nt < 8; nt++) {
            unsigned b0 = Ws[k0 + tg][nt * 8 + g];
            unsigned b1 = Ws[k0 + tg + 4][nt * 8 + g];
            asm("mma.sync.aligned.m16n8k8.row.col.f32.tf32.tf32.f32 "
                "{%0,%1,%2,%3}, {%4,%5,%6,%7}, {%8,%9}, {%0,%1,%2,%3};"
                : "+f"(acc[nt][0]), "+f"(acc[nt][1]),
                  "+f"(acc[nt][2]), "+f"(acc[nt][3])
                : "r"(a0), "r"(a1), "r"(a2), "r"(a3), "r"(b0), "r"(b1));
        }
    }

    float s_lo = 1.f, s_hi = 1.f;
    if (r_lo < n) {
        int dg = g_deg_out[r_lo];
        s_lo = rsqrtf((float)(dg > 0 ? dg : 1));
    }
    if (r_hi < n) {
        int dg = g_deg_out[r_hi];
        s_hi = rsqrtf((float)(dg > 0 ? dg : 1));
    }
    #pragma unroll
    for (int nt = 0; nt < 8; nt++) {
        int col = nt * 8 + 2 * tg;
        if (r_lo < n) {
            __half2 h = __floats2half2_rn(acc[nt][0] * s_lo, acc[nt][1] * s_lo);
            *(__half2*)&g_xws_h[(size_t)r_lo * OUTF + col] = h;
        }
        if (r_hi < n) {
            __half2 h = __floats2half2_rn(acc[nt][2] * s_hi, acc[nt][3] * s_hi);
            *(__half2*)&g_xws_h[(size_t)r_hi * OUTF + col] = h;
        }
    }
}

// ---------------------------------------------------------------------------
// Aggregate: one warp per dst node (R7 scheme), but MLP deepened to 8:
// 8 independent 128B-row gathers in flight per warp batch to cover the
// ~250-cycle random L2-hit latency. fp32 accumulation, fused finalize.
// ---------------------------------------------------------------------------
__global__ __launch_bounds__(256) void aggregate_kernel(
    float* __restrict__ out, const float* __restrict__ b, int n) {
    int warp = (blockIdx.x * blockDim.x + threadIdx.x) >> 5;
    if (warp >= n) return;
    int lane = threadIdx.x & 31;

    int start = g_row_off[warp];
    int deg   = g_deg_in[warp];

    float accx = 0.f, accy = 0.f;
    const __half2* base = (const __half2*)g_xws_h;

    for (int e0 = 0; e0 < deg; e0 += 32) {
        int me  = e0 + lane;
        int s   = (me < deg) ? __ldg(&g_csr_src[start + me]) : 0;
        int cnt = deg - e0; if (cnt > 32) cnt = 32;
        int j = 0;
        #pragma unroll 1
        for (; j + 8 <= cnt; j += 8) {
            int si[8];
            #pragma unroll
            for (int q = 0; q < 8; q++)
                si[q] = __shfl_sync(0xffffffffu, s, j + q);
            __half2 v[8];
            #pragma unroll
            for (int q = 0; q < 8; q++)
                v[q] = __ldg(base + (size_t)si[q] * 32 + lane);
            #pragma unroll
            for (int q = 0; q < 8; q++) {
                float2 f = __half22float2(v[q]);
                accx += f.x;
                accy += f.y;
            }
        }
        for (; j < cnt; j++) {
            int sj = __shfl_sync(0xffffffffu, s, j);
            float2 f = __half22float2(__ldg(base + (size_t)sj * 32 + lane));
            accx += f.x;
            accy += f.y;
        }
    }

    float sc = rsqrtf((float)(deg > 0 ? deg : 1));
    float2 bb = __ldg((const float2*)b + lane);
    float2 r;
    r.x = fmaxf(fmaf(accx, sc, bb.x), 0.f);
    r.y = fmaxf(fmaf(accy, sc, bb.y), 0.f);
    ((float2*)out)[(size_t)warp * 32 + lane] = r;
}

// ---------------------------------------------------------------------------
extern "C" void kernel_launch(void* const* d_in, const int* in_sizes, int n_in,
                              void* d_out, int out_size) {
    const float* in_feat = (const float*)d_in[0];
    const int*   src     = (const int*)d_in[1];
    const int*   dst     = (const int*)d_in[2];
    const float* W       = (const float*)d_in[3];
    const float* b       = (const float*)d_in[4];
    float*       out     = (float*)d_out;

    int n = in_sizes[0] / INF;
    int E = in_sizes[1];

    zero_kernel<<<512, 256>>>();
    degree_kernel<<<2048, 256>>>(src, dst, E);
    scan_local_kernel<<<NBLK, SCAN_B>>>();
    scan_blocks_kernel<<<1, 128>>>();
    scan_add_kernel<<<NBLK, SCAN_B>>>();
    csr_fill_kernel<<<2048, 256>>>(src, dst, E);
    gemm_mma_kernel<<<(n + 127) / 128, 256>>>(in_feat, W, n);
    aggregate_kernel<<<(n * 32 + 255) / 256, 256>>>(out, b, n);
}